// round 8
// baseline (speedup 1.0000x reference)
#include <cuda_runtime.h>
#include <cuda_bf16.h>
#include <cstdint>

// Shapes: X[131072,256], W1[256,384], b1[384], W2[384,64], b2[64],
//         phi[5,64] i32, pi[5,64,16], out[131072,16]
#define NF  256
#define NH  384
#define NL  64
#define NO  16
#define NE  5

#define KS  136          // padded smem k-stride in bf16 elems (272 B rows)
#define NT  512          // threads per CTA

// ---------------------------------------------------------------------------
// Weight tables: bf16 hi/lo, transposed to [n][k] tiles (static device mem)
// ---------------------------------------------------------------------------
__device__ __nv_bfloat16 gW1T[2][98304];
__device__ __nv_bfloat16 gW2T[2][24576];

__global__ void conv_w(const float* __restrict__ W1, const float* __restrict__ W2) {
    int idx = blockIdx.x * 256 + threadIdx.x;
    if (idx < 98304) {
        int k  = idx & 127;
        int n  = (idx >> 7) & 127;
        int kc = (idx >> 14) & 1;
        int nc = idx >> 15;                       // 0..2
        float v = W1[(size_t)(kc * 128 + k) * NH + nc * 128 + n];
        __nv_bfloat16 hi = __float2bfloat16(v);
        __nv_bfloat16 lo = __float2bfloat16(v - __bfloat162float(hi));
        gW1T[0][idx] = hi;
        gW1T[1][idx] = lo;
    }
    if (idx < 24576) {
        int k  = idx & 127;
        int n  = (idx >> 7) & 63;
        int kc = idx >> 13;                       // 0..2
        float v = W2[(size_t)(kc * 128 + k) * NL + n];
        __nv_bfloat16 hi = __float2bfloat16(v);
        __nv_bfloat16 lo = __float2bfloat16(v - __bfloat162float(hi));
        gW2T[0][idx] = hi;
        gW2T[1][idx] = lo;
    }
}

// ---------------------------------------------------------------------------
// PTX helpers
// ---------------------------------------------------------------------------
__device__ __forceinline__ uint32_t smem_u32(const void* p) {
    uint32_t a;
    asm("{ .reg .u64 t; cvta.to.shared.u64 t, %1; cvt.u32.u64 %0, t; }"
        : "=r"(a) : "l"(p));
    return a;
}

#define LDM_X4(r, addr) \
    asm volatile("ldmatrix.sync.aligned.m8n8.x4.shared.b16 {%0,%1,%2,%3}, [%4];" \
        : "=r"((r)[0]), "=r"((r)[1]), "=r"((r)[2]), "=r"((r)[3]) : "r"(addr))

__device__ __forceinline__ void mma_bf16(float* c, const uint32_t* a, const uint32_t* b) {
    asm volatile("mma.sync.aligned.m16n8k16.row.col.f32.bf16.bf16.f32 "
        "{%0,%1,%2,%3}, {%4,%5,%6,%7}, {%8,%9}, {%0,%1,%2,%3};"
        : "+f"(c[0]), "+f"(c[1]), "+f"(c[2]), "+f"(c[3])
        : "r"(a[0]), "r"(a[1]), "r"(a[2]), "r"(a[3]), "r"(b[0]), "r"(b[1]));
}

__device__ __forceinline__ float fsigmoid(float v) {
    return 1.0f / (1.0f + __expf(-v));
}

// ---------------------------------------------------------------------------
// SMEM layout (bytes) — unchanged from R7
// ---------------------------------------------------------------------------
#define SM_X    0
#define SM_XLO  34816
#define SM_W1   69632
#define SM_W1LO 104448
#define SM_LAT  69632
#define SM_W2   139264
#define SM_W2LO 156672
#define SM_PI   174080
#define SM_PHI  194560
#define SM_B1   195840
#define SM_B2   197376
#define SMEM_TOTAL 197632

__global__ __launch_bounds__(NT, 1)
void fused_all(const float* __restrict__ X, const float* __restrict__ b1,
               const float* __restrict__ b2, const int* __restrict__ phi,
               const float* __restrict__ pi, float* __restrict__ out) {
    extern __shared__ char smem[];
    const uint32_t sb = smem_u32(smem);
    const int tid = threadIdx.x;
    const int wid = tid >> 5;          // 0..15
    const int lane = tid & 31;
    const int g = lane >> 2;           // 0..7
    const int tg = lane & 3;           // 0..3
    const size_t rowBase = (size_t)blockIdx.x * 128;

    // ldmatrix per-lane selectors
    const int a_dr = lane & 15;
    const int a_dc = (lane >> 4) * 8;
    const int b_dn = (lane & 7) + (lane >> 4) * 8;
    const int b_dk = ((lane >> 3) & 1) * 8;

    // GEMM1: 4x4 warp grid, each warp 32 rows x 32 cols
    const int wm = (wid & 3) * 32;
    const int wn = (wid >> 2) * 32;
    // GEMM2: 8x2 warp grid, each warp 16 rows x 32 cols
    const int wm2 = (wid & 7) * 16;
    const int wn2 = (wid >> 3) * 32;

    // ---- stage constants ----
    {
        float4* pis4 = (float4*)(smem + SM_PI);
        const float4* pi4 = (const float4*)pi;
        for (int i = tid; i < 1280; i += NT) pis4[i] = pi4[i];
        int* phis = (int*)(smem + SM_PHI);
        if (tid < NE * NL) phis[tid] = phi[tid];
        float* b1s = (float*)(smem + SM_B1);
        if (tid < NH) b1s[tid] = b1[tid];
        float* b2s = (float*)(smem + SM_B2);
        if (tid < NL) b2s[tid] = b2[tid];
    }

    const float* b1s = (const float*)(smem + SM_B1);
    const float* b2s = (const float*)(smem + SM_B2);

    float acc2[4][4];
#pragma unroll
    for (int n = 0; n < 4; n++)
#pragma unroll
        for (int r = 0; r < 4; r++) acc2[n][r] = 0.0f;

    // X staging: thread -> (row, 32-col quarter)
    const int xr = tid >> 2;           // 0..127
    const int xc = (tid & 3) * 32;     // 0,32,64,96

#pragma unroll 1
    for (int nc = 0; nc < 3; nc++) {
        float acc1[2][4][4];
#pragma unroll
        for (int m = 0; m < 2; m++)
#pragma unroll
            for (int n = 0; n < 4; n++)
#pragma unroll
                for (int r = 0; r < 4; r++) acc1[m][n][r] = 0.0f;

#pragma unroll 1
        for (int kc = 0; kc < 2; kc++) {
            __syncthreads();

            // ---- stage X chunk [128][128] fp32 -> bf16 hi/lo ----
            const float* Xp = X + (rowBase + xr) * NF + kc * 128 + xc;
            char* xhi = smem + SM_X   + xr * (KS * 2) + xc * 2;
            char* xlo = smem + SM_XLO + xr * (KS * 2) + xc * 2;
#pragma unroll
            for (int i = 0; i < 8; i++) {
                float4 v = *(const float4*)(Xp + i * 4);
                __nv_bfloat162 h01 = __float22bfloat162_rn(make_float2(v.x, v.y));
                __nv_bfloat162 h23 = __float22bfloat162_rn(make_float2(v.z, v.w));
                __nv_bfloat162 l01 = __float22bfloat162_rn(make_float2(
                    v.x - __bfloat162float(h01.x), v.y - __bfloat162float(h01.y)));
                __nv_bfloat162 l23 = __float22bfloat162_rn(make_float2(
                    v.z - __bfloat162float(h23.x), v.w - __bfloat162float(h23.y)));
                *(uint32_t*)(xhi + i * 8)     = *(uint32_t*)&h01;
                *(uint32_t*)(xhi + i * 8 + 4) = *(uint32_t*)&h23;
                *(uint32_t*)(xlo + i * 8)     = *(uint32_t*)&l01;
                *(uint32_t*)(xlo + i * 8 + 4) = *(uint32_t*)&l23;
            }

            // ---- stage W1 tiles (copy from pre-split tables) ----
#pragma unroll
            for (int s = 0; s < 2; s++) {
                const uint4* src = (const uint4*)(&gW1T[s][(nc * 2 + kc) * 16384]);
                char* dst = smem + (s ? SM_W1LO : SM_W1);
#pragma unroll
                for (int i = 0; i < 4; i++) {
                    int j = tid + i * NT;
                    int n = j >> 4, kv = j & 15;
                    *(uint4*)(dst + n * (KS * 2) + kv * 16) = src[j];
                }
            }
            __syncthreads();

            // ---- GEMM1 mma: 3 passes (hi*hi, hi*lo, lo*hi) ----
#pragma unroll
            for (int pass = 0; pass < 3; pass++) {
                uint32_t Ab = sb + (pass == 2 ? SM_XLO : SM_X)
                            + ((wm + a_dr) * KS + a_dc) * 2;
                uint32_t Bb = sb + (pass == 1 ? SM_W1LO : SM_W1)
                            + ((wn + b_dn) * KS + b_dk) * 2;
#pragma unroll
                for (int k16 = 0; k16 < 8; k16++) {
                    uint32_t a[2][4];
                    LDM_X4(a[0], Ab + k16 * 32);
                    LDM_X4(a[1], Ab + k16 * 32 + 16 * KS * 2);
                    uint32_t bq[2][4];
#pragma unroll
                    for (int p = 0; p < 2; p++)
                        LDM_X4(bq[p], Bb + k16 * 32 + p * 16 * KS * 2);
#pragma unroll
                    for (int m = 0; m < 2; m++)
#pragma unroll
                        for (int n = 0; n < 4; n++)
                            mma_bf16(acc1[m][n], a[m], &bq[n >> 1][(n & 1) * 2]);
                }
            }
        }
        __syncthreads();   // GEMM1 reads of W1s done -> overwrite with Hs

        // ---- epilogue1: h = sigmoid(acc1 + b1) -> Hs hi/lo ----
#pragma unroll
        for (int m = 0; m < 2; m++) {
            int row0 = wm + m * 16 + g;
#pragma unroll
            for (int n = 0; n < 4; n++) {
                int col = wn + n * 8 + 2 * tg;
                float bb0 = b1s[nc * 128 + col];
                float bb1 = b1s[nc * 128 + col + 1];
                float f0 = fsigmoid(acc1[m][n][0] + bb0);
                float f1 = fsigmoid(acc1[m][n][1] + bb1);
                float f2 = fsigmoid(acc1[m][n][2] + bb0);
                float f3 = fsigmoid(acc1[m][n][3] + bb1);
                __nv_bfloat162 h01 = __float22bfloat162_rn(make_float2(f0, f1));
                __nv_bfloat162 h23 = __float22bfloat162_rn(make_float2(f2, f3));
                __nv_bfloat162 l01 = __float22bfloat162_rn(make_float2(
                    f0 - __bfloat162float(h01.x), f1 - __bfloat162float(h01.y)));
                __nv_bfloat162 l23 = __float22bfloat162_rn(make_float2(
                    f2 - __bfloat162float(h23.x), f3 - __bfloat162float(h23.y)));
                *(uint32_t*)(smem + SM_W1   + (row0 * KS + col) * 2)       = *(uint32_t*)&h01;
                *(uint32_t*)(smem + SM_W1   + ((row0 + 8) * KS + col) * 2) = *(uint32_t*)&h23;
                *(uint32_t*)(smem + SM_W1LO + (row0 * KS + col) * 2)       = *(uint32_t*)&l01;
                *(uint32_t*)(smem + SM_W1LO + ((row0 + 8) * KS + col) * 2) = *(uint32_t*)&l23;
            }
        }

        // ---- stage W2 chunk ----
#pragma unroll
        for (int s = 0; s < 2; s++) {
            const uint4* src = (const uint4*)(&gW2T[s][nc * 8192]);
            char* dst = smem + (s ? SM_W2LO : SM_W2);
#pragma unroll
            for (int i = 0; i < 2; i++) {
                int j = tid + i * NT;
                int n = j >> 4, kv = j & 15;
                *(uint4*)(dst + n * (KS * 2) + kv * 16) = src[j];
            }
        }
        __syncthreads();

        // ---- GEMM2 mma: latacc += Hc @ W2c, 3 passes ----
#pragma unroll
        for (int pass = 0; pass < 3; pass++) {
            uint32_t Ab = sb + (pass == 2 ? SM_W1LO : SM_W1)
                        + ((wm2 + a_dr) * KS + a_dc) * 2;
            uint32_t Bb = sb + (pass == 1 ? SM_W2LO : SM_W2)
                        + ((wn2 + b_dn) * KS + b_dk) * 2;
#pragma unroll
            for (int k16 = 0; k16 < 8; k16++) {
                uint32_t a[4];
                LDM_X4(a, Ab + k16 * 32);
                uint32_t bq[2][4];
#pragma unroll
                for (int p = 0; p < 2; p++)
                    LDM_X4(bq[p], Bb + k16 * 32 + p * 16 * KS * 2);
#pragma unroll
                for (int n = 0; n < 4; n++)
                    mma_bf16(acc2[n], a, &bq[n >> 1][(n & 1) * 2]);
            }
        }
    }
    __syncthreads();   // GEMM2 reads of Hs done -> lat overlays region

    // ---- latent = sigmoid(acc2 + b2) -> lat smem ----
    float* lat = (float*)(smem + SM_LAT);
#pragma unroll
    for (int n = 0; n < 4; n++) {
        int c0 = wn2 + n * 8 + 2 * tg;
        lat[(wm2 + g) * 65 + c0]         = fsigmoid(acc2[n][0] + b2s[c0]);
        lat[(wm2 + g) * 65 + c0 + 1]     = fsigmoid(acc2[n][1] + b2s[c0 + 1]);
        lat[(wm2 + g + 8) * 65 + c0]     = fsigmoid(acc2[n][2] + b2s[c0]);
        lat[(wm2 + g + 8) * 65 + c0 + 1] = fsigmoid(acc2[n][3] + b2s[c0 + 1]);
    }
    __syncthreads();

    // ---- tree + pi contraction: 4 threads per row, 4 outputs each ----
    {
        const int row = tid & 127;
        const int obase = (tid >> 7) * 4;   // 0,4,8,12
        const float* latrow = lat + row * 65;
        const int* phis = (const int*)(smem + SM_PHI);
        const float* pis = (const float*)(smem + SM_PI);
        float accO[4] = {0.0f, 0.0f, 0.0f, 0.0f};

#pragma unroll 1
        for (int e = 0; e < NE; e++) {
            const int* phie = phis + e * NL;
            float mu[64];
            mu[0] = 1.0f;
#pragma unroll
            for (int lev = 0; lev < 6; lev++) {
#pragma unroll
                for (int j = (1 << lev) - 1; j >= 0; j--) {
                    int node = (1 << lev) + j;
                    float d = latrow[phie[node]];
                    float p = mu[j];
                    mu[2 * j + 1] = p * (1.0f - d);
                    mu[2 * j]     = p * d;
                }
            }
            const float* pie = pis + e * NL * NO;
#pragma unroll
            for (int l = 0; l < NL; l++) {
                float m = mu[l];
                const float* pr = pie + l * NO + obase;
#pragma unroll
                for (int o = 0; o < 4; o++)
                    accO[o] = fmaf(m, pr[o], accO[o]);
            }
        }
        float4 o0;
        o0.x = accO[0] * 0.2f; o0.y = accO[1] * 0.2f;
        o0.z = accO[2] * 0.2f; o0.w = accO[3] * 0.2f;
        *(float4*)(out + (rowBase + row) * NO + obase) = o0;
    }
}

// ---------------------------------------------------------------------------
extern "C" void kernel_launch(void* const* d_in, const int* in_sizes, int n_in,
                              void* d_out, int out_size) {
    const float* X   = (const float*)d_in[0];
    const float* W1  = (const float*)d_in[1];
    const float* b1  = (const float*)d_in[2];
    const float* W2  = (const float*)d_in[3];
    const float* b2  = (const float*)d_in[4];
    const int*   phi = (const int*)d_in[5];
    const float* pi  = (const float*)d_in[6];
    float* out = (float*)d_out;

    const int N = in_sizes[0] / NF;   // 131072

    cudaFuncSetAttribute(fused_all, cudaFuncAttributeMaxDynamicSharedMemorySize,
                         SMEM_TOTAL);

    conv_w<<<384, 256>>>(W1, W2);
    fused_all<<<N / 128, NT, SMEM_TOTAL>>>(X, b1, b2, phi, pi, out);
}

// round 9
// speedup vs baseline: 1.0228x; 1.0228x over previous
#include <cuda_runtime.h>
#include <cuda_bf16.h>
#include <cstdint>

// Shapes: X[131072,256], W1[256,384], b1[384], W2[384,64], b2[64],
//         phi[5,64] i32, pi[5,64,16], out[131072,16]
#define NF  256
#define NH  384
#define NL  64
#define NO  16
#define NE  5

#define KS2 72           // k-stride (elems) for 64-k tiles   (144 B rows)
#define KS  136          // k-stride (elems) for Hs (128-k)   (272 B rows)

// ---------------------------------------------------------------------------
// Pre-split global tables (bf16 hi/lo), written by prep kernels each launch.
//   gXhi/gXlo : elementwise split of X, plain [131072*256] layout
//   gW1  : [s][nc(3)][k4(4)][n=128][k=64]   (B operand tiles, copy-ready)
//   gW2  : [s][nc(3)][n=64][k=128]
// ---------------------------------------------------------------------------
__device__ __align__(16) __nv_bfloat16 gXhi[131072UL * 256UL];
__device__ __align__(16) __nv_bfloat16 gXlo[131072UL * 256UL];
__device__ __align__(16) __nv_bfloat16 gW1[2][98304];
__device__ __align__(16) __nv_bfloat16 gW2[2][24576];

__global__ void prep_x(const float* __restrict__ X) {
    size_t idx = (size_t)blockIdx.x * 256 + threadIdx.x;   // one float4 each
    float4 v = *(const float4*)(X + idx * 4);
    __nv_bfloat162 h01 = __float22bfloat162_rn(make_float2(v.x, v.y));
    __nv_bfloat162 h23 = __float22bfloat162_rn(make_float2(v.z, v.w));
    __nv_bfloat162 l01 = __float22bfloat162_rn(make_float2(
        v.x - __bfloat162float(h01.x), v.y - __bfloat162float(h01.y)));
    __nv_bfloat162 l23 = __float22bfloat162_rn(make_float2(
        v.z - __bfloat162float(h23.x), v.w - __bfloat162float(h23.y)));
    uint2 hp, lp;
    hp.x = *(uint32_t*)&h01; hp.y = *(uint32_t*)&h23;
    lp.x = *(uint32_t*)&l01; lp.y = *(uint32_t*)&l23;
    *(uint2*)(gXhi + idx * 4) = hp;
    *(uint2*)(gXlo + idx * 4) = lp;
}

__global__ void prep_w(const float* __restrict__ W1, const float* __restrict__ W2) {
    int idx = blockIdx.x * 256 + threadIdx.x;
    if (idx < 98304) {
        int k  = idx & 63;
        int n  = (idx >> 6) & 127;
        int k4 = (idx >> 13) & 3;
        int nc = idx >> 15;                      // 0..2
        float v = W1[(size_t)(k4 * 64 + k) * NH + nc * 128 + n];
        __nv_bfloat16 hi = __float2bfloat16(v);
        __nv_bfloat16 lo = __float2bfloat16(v - __bfloat162float(hi));
        gW1[0][idx] = hi;
        gW1[1][idx] = lo;
    }
    if (idx < 24576) {
        int k  = idx & 127;
        int n  = (idx >> 7) & 63;
        int nc = idx >> 13;                      // 0..2
        float v = W2[(size_t)(nc * 128 + k) * NL + n];
        __nv_bfloat16 hi = __float2bfloat16(v);
        __nv_bfloat16 lo = __float2bfloat16(v - __bfloat162float(hi));
        gW2[0][idx] = hi;
        gW2[1][idx] = lo;
    }
}

// ---------------------------------------------------------------------------
// PTX helpers
// ---------------------------------------------------------------------------
__device__ __forceinline__ uint32_t smem_u32(const void* p) {
    uint32_t a;
    asm("{ .reg .u64 t; cvta.to.shared.u64 t, %1; cvt.u32.u64 %0, t; }"
        : "=r"(a) : "l"(p));
    return a;
}

#define CP16(dst, src) \
    asm volatile("cp.async.cg.shared.global [%0], [%1], 16;" :: "r"(dst), "l"(src))
#define CP_COMMIT() asm volatile("cp.async.commit_group;" ::: "memory")
#define CP_WAIT1()  asm volatile("cp.async.wait_group 1;" ::: "memory")
#define CP_WAIT0()  asm volatile("cp.async.wait_group 0;" ::: "memory")

#define LDM_X4(r, addr) \
    asm volatile("ldmatrix.sync.aligned.m8n8.x4.shared.b16 {%0,%1,%2,%3}, [%4];" \
        : "=r"((r)[0]), "=r"((r)[1]), "=r"((r)[2]), "=r"((r)[3]) : "r"(addr))

__device__ __forceinline__ void mma_bf16(float* c, const uint32_t* a, const uint32_t* b) {
    asm volatile("mma.sync.aligned.m16n8k16.row.col.f32.bf16.bf16.f32 "
        "{%0,%1,%2,%3}, {%4,%5,%6,%7}, {%8,%9}, {%0,%1,%2,%3};"
        : "+f"(c[0]), "+f"(c[1]), "+f"(c[2]), "+f"(c[3])
        : "r"(a[0]), "r"(a[1]), "r"(a[2]), "r"(a[3]), "r"(b[0]), "r"(b[1]));
}

__device__ __forceinline__ float fsigmoid(float v) {
    return 1.0f / (1.0f + __expf(-v));
}

// ---------------------------------------------------------------------------
// SMEM layout (bytes):
//   pipeline buffers, 2 stages of 73728:
//     per stage: [XH 18432][XL 18432][WH 18432][WL 18432]  (tiles 128x64, KS2)
//   SM_BUF0 = 0,  SM_BUF1 = 73728
//   W2 staged into SM_BUF0 during GEMM2: [hi 17408][lo 17408] (64n x KS)
//   SM_HS  = 147456 : h tile [128][KS] hi, lo at +34816  (total 69632)
//   SM_LAT = 147456 : latent [128][65] f32 (overlays Hs after last GEMM2)
//   SM_PHI = 217088 (1280) | SM_B1 = 218368 (1536) | SM_B2 = 219904 (256)
// ---------------------------------------------------------------------------
#define XBUF    18432
#define STG     73728
#define SM_BUF0 0
#define SM_BUF1 73728
#define SM_HS   147456
#define SM_LAT  147456
#define SM_PHI  217088
#define SM_B1   218368
#define SM_B2   219904
#define SMEM_TOTAL 220160

// stage copy: X tile [128 rows][64 k] hi/lo + W1 tile [128 n][64 k] hi/lo
__device__ __forceinline__ void issue_g1(uint32_t sbuf, int nc, int k4,
                                         size_t rowBase, int tid) {
#pragma unroll
    for (int i = 0; i < 4; i++) {
        int j = tid + i * 256;
        int row = j >> 3, c = j & 7;
        const __nv_bfloat16* sh = gXhi + (rowBase + row) * NF + k4 * 64 + c * 8;
        const __nv_bfloat16* sl = gXlo + (rowBase + row) * NF + k4 * 64 + c * 8;
        uint32_t d = sbuf + row * 144 + c * 16;
        CP16(d, sh);
        CP16(d + XBUF, sl);
    }
    const int wbase = ((nc * 4 + k4) * 128) * 64;
#pragma unroll
    for (int i = 0; i < 4; i++) {
        int j = tid + i * 256;
        int n = j >> 3, c = j & 7;
        uint32_t d = sbuf + 2 * XBUF + n * 144 + c * 16;
        CP16(d,        gW1[0] + wbase + n * 64 + c * 8);
        CP16(d + XBUF, gW1[1] + wbase + n * 64 + c * 8);
    }
    CP_COMMIT();
}

__device__ __forceinline__ void issue_w2(uint32_t sb, int nc, int tid) {
#pragma unroll
    for (int i = 0; i < 4; i++) {
        int j = tid + i * 256;
        int n = j >> 4, c = j & 15;
        uint32_t d = sb + SM_BUF0 + n * 272 + c * 16;
        CP16(d,         gW2[0] + (nc * 64 + n) * 128 + c * 8);
        CP16(d + 17408, gW2[1] + (nc * 64 + n) * 128 + c * 8);
    }
    CP_COMMIT();
}

__global__ __launch_bounds__(256, 1)
void fused_all(const float* __restrict__ b1, const float* __restrict__ b2,
               const int* __restrict__ phi, const float* __restrict__ pi,
               float* __restrict__ out) {
    extern __shared__ char smem[];
    const uint32_t sb = smem_u32(smem);
    const int tid = threadIdx.x;
    const int wid = tid >> 5;
    const int lane = tid & 31;
    const int g = lane >> 2;
    const int tg = lane & 3;
    const size_t rowBase = (size_t)blockIdx.x * 128;

    const int a_dr = lane & 15;
    const int a_dc = (lane >> 4) * 8;
    const int b_dn = (lane & 7) + (lane >> 4) * 8;
    const int b_dk = ((lane >> 3) & 1) * 8;

    // GEMM1: 4x2 warp grid, 32 rows x 64 cols per warp
    const int wm = (wid & 3) * 32;
    const int wn = (wid >> 2) * 64;
    // GEMM2: 8x1 grid, 16 rows x 64 cols per warp
    const int wm2 = wid * 16;

    // ---- stage constants (disjoint smem regions) ----
    {
        int* phis = (int*)(smem + SM_PHI);
        for (int i = tid; i < NE * NL; i += 256) phis[i] = phi[i];
        float* b1s = (float*)(smem + SM_B1);
        for (int i = tid; i < NH; i += 256) b1s[i] = b1[i];
        float* b2s = (float*)(smem + SM_B2);
        if (tid < NL) b2s[tid] = b2[tid];
    }

    const float* b1s = (const float*)(smem + SM_B1);
    const float* b2s = (const float*)(smem + SM_B2);

    float acc2[8][4];
#pragma unroll
    for (int n = 0; n < 8; n++)
#pragma unroll
        for (int r = 0; r < 4; r++) acc2[n][r] = 0.0f;

#pragma unroll 1
    for (int nc = 0; nc < 3; nc++) {
        float acc1[2][8][4];
#pragma unroll
        for (int m = 0; m < 2; m++)
#pragma unroll
            for (int n = 0; n < 8; n++)
#pragma unroll
                for (int r = 0; r < 4; r++) acc1[m][n][r] = 0.0f;

        // pipeline prologue: stages 0 and 1
        issue_g1(sb + SM_BUF0, nc, 0, rowBase, tid);
        issue_g1(sb + SM_BUF1, nc, 1, rowBase, tid);

#pragma unroll 1
        for (int k4 = 0; k4 < 4; k4++) {
            CP_WAIT1();
            __syncthreads();

            const uint32_t buf = sb + ((k4 & 1) ? SM_BUF1 : SM_BUF0);
            // ---- GEMM1 mma on stage k4: 3 passes ----
#pragma unroll
            for (int pass = 0; pass < 3; pass++) {
                uint32_t Ab = buf + (pass == 2 ? XBUF : 0)
                            + ((wm + a_dr) * KS2 + a_dc) * 2;
                uint32_t Bb = buf + 2 * XBUF + (pass == 1 ? XBUF : 0)
                            + ((wn + b_dn) * KS2 + b_dk) * 2;
#pragma unroll
                for (int k16 = 0; k16 < 4; k16++) {
                    uint32_t a[2][4];
                    LDM_X4(a[0], Ab + k16 * 32);
                    LDM_X4(a[1], Ab + k16 * 32 + 16 * KS2 * 2);
                    uint32_t bq[4][4];
#pragma unroll
                    for (int p = 0; p < 4; p++)
                        LDM_X4(bq[p], Bb + k16 * 32 + p * 16 * KS2 * 2);
#pragma unroll
                    for (int m = 0; m < 2; m++)
#pragma unroll
                        for (int n = 0; n < 8; n++)
                            mma_bf16(acc1[m][n], a[m], &bq[n >> 1][(n & 1) * 2]);
                }
            }
            __syncthreads();            // all warps done reading this buffer

            if (k4 == 0)      issue_g1(sb + SM_BUF0, nc, 2, rowBase, tid);
            else if (k4 == 1) issue_g1(sb + SM_BUF1, nc, 3, rowBase, tid);
            else if (k4 == 2) issue_w2(sb, nc, tid);   // into BUF0 (free now)
        }

        // ---- epilogue1: h = sigmoid(acc1 + b1) -> Hs hi/lo (dedicated) ----
#pragma unroll
        for (int m = 0; m < 2; m++) {
            int row0 = wm + m * 16 + g;
#pragma unroll
            for (int n = 0; n < 8; n++) {
                int col = wn + n * 8 + 2 * tg;          // k index for GEMM2
                float bb0 = b1s[nc * 128 + col];
                float bb1 = b1s[nc * 128 + col + 1];
                float f0 = fsigmoid(acc1[m][n][0] + bb0);
                float f1 = fsigmoid(acc1[m][n][1] + bb1);
                float f2 = fsigmoid(acc1[m][n][2] + bb0);
                float f3 = fsigmoid(acc1[m][n][3] + bb1);
                __nv_bfloat162 h01 = __float22bfloat162_rn(make_float2(f0, f1));
                __nv_bfloat162 h23 = __float22bfloat162_rn(make_float2(f2, f3));
                __nv_bfloat162 l01 = __float22bfloat162_rn(make_float2(
                    f0 - __bfloat162float(h01.x), f1 - __bfloat162float(h01.y)));
                __nv_bfloat162 l23 = __float22bfloat162_rn(make_float2(
                    f2 - __bfloat162float(h23.x), f3 - __bfloat162float(h23.y)));
                *(uint32_t*)(smem + SM_HS + (row0 * KS + col) * 2)               = *(uint32_t*)&h01;
                *(uint32_t*)(smem + SM_HS + ((row0 + 8) * KS + col) * 2)         = *(uint32_t*)&h23;
                *(uint32_t*)(smem + SM_HS + 34816 + (row0 * KS + col) * 2)       = *(uint32_t*)&l01;
                *(uint32_t*)(smem + SM_HS + 34816 + ((row0 + 8) * KS + col) * 2) = *(uint32_t*)&l23;
            }
        }
        CP_WAIT0();            // W2 arrived
        __syncthreads();       // Hs + W2 visible to all

        // ---- GEMM2 mma: acc2 += Hc @ W2c, 3 passes ----
#pragma unroll
        for (int pass = 0; pass < 3; pass++) {
            uint32_t Ab = sb + SM_HS + (pass == 2 ? 34816 : 0)
                        + ((wm2 + a_dr) * KS + a_dc) * 2;
            uint32_t Bb = sb + SM_BUF0 + (pass == 1 ? 17408 : 0)
                        + (b_dn * KS + b_dk) * 2;
#pragma unroll
            for (int k16 = 0; k16 < 8; k16++) {
                uint32_t a[4];
                LDM_X4(a, Ab + k16 * 32);
                uint32_t bq[4][4];
#pragma unroll
                for (int p = 0; p < 4; p++)
                    LDM_X4(bq[p], Bb + k16 * 32 + p * 16 * KS * 2);
#pragma unroll
                for (int n = 0; n < 8; n++)
                    mma_bf16(acc2[n], a, &bq[n >> 1][(n & 1) * 2]);
            }
        }
        __syncthreads();       // all done reading W2/Hs before next-nc reuse
    }

    // ---- latent = sigmoid(acc2 + b2) -> lat (overlays Hs region) ----
    float* lat = (float*)(smem + SM_LAT);
#pragma unroll
    for (int n = 0; n < 8; n++) {
        int c0 = n * 8 + 2 * tg;
        lat[(wm2 + g) * 65 + c0]         = fsigmoid(acc2[n][0] + b2s[c0]);
        lat[(wm2 + g) * 65 + c0 + 1]     = fsigmoid(acc2[n][1] + b2s[c0 + 1]);
        lat[(wm2 + g + 8) * 65 + c0]     = fsigmoid(acc2[n][2] + b2s[c0]);
        lat[(wm2 + g + 8) * 65 + c0 + 1] = fsigmoid(acc2[n][3] + b2s[c0 + 1]);
    }
    __syncthreads();

    // ---- tree + pi contraction (pi via L1-cached global) ----
    {
        const int row = tid & 127;
        const int obase = (tid >> 7) * 8;   // 0 or 8
        const float* latrow = lat + row * 65;
        const int* phis = (const int*)(smem + SM_PHI);
        float accO[8];
#pragma unroll
        for (int o = 0; o < 8; o++) accO[o] = 0.0f;

#pragma unroll 1
        for (int e = 0; e < NE; e++) {
            const int* phie = phis + e * NL;
            float mu[64];
            mu[0] = 1.0f;
#pragma unroll
            for (int lev = 0; lev < 6; lev++) {
#pragma unroll
                for (int j = (1 << lev) - 1; j >= 0; j--) {
                    int node = (1 << lev) + j;
                    float d = latrow[phie[node]];
                    float p = mu[j];
                    mu[2 * j + 1] = p * (1.0f - d);
                    mu[2 * j]     = p * d;
                }
            }
            const float* pie = pi + e * NL * NO + obase;
#pragma unroll
            for (int l = 0; l < NL; l++) {
                float m = mu[l];
                float4 p0 = __ldg((const float4*)(pie + l * NO));
                float4 p1 = __ldg((const float4*)(pie + l * NO + 4));
                accO[0] = fmaf(m, p0.x, accO[0]);
                accO[1] = fmaf(m, p0.y, accO[1]);
                accO[2] = fmaf(m, p0.z, accO[2]);
                accO[3] = fmaf(m, p0.w, accO[3]);
                accO[4] = fmaf(m, p1.x, accO[4]);
                accO[5] = fmaf(m, p1.y, accO[5]);
                accO[6] = fmaf(m, p1.z, accO[6]);
                accO[7] = fmaf(m, p1.w, accO[7]);
            }
        }
        float4 o0, o1;
        o0.x = accO[0] * 0.2f; o0.y = accO[1] * 0.2f;
        o0.z = accO[2] * 0.2f; o0.w = accO[3] * 0.2f;
        o1.x = accO[4] * 0.2f; o1.y = accO[5] * 0.2f;
        o1.z = accO[6] * 0.2f; o1.w = accO[7] * 0.2f;
        float* op = out + (rowBase + row) * NO + obase;
        *(float4*)op       = o0;
        *(float4*)(op + 4) = o1;
    }
}

// ---------------------------------------------------------------------------
extern "C" void kernel_launch(void* const* d_in, const int* in_sizes, int n_in,
                              void* d_out, int out_size) {
    const float* X   = (const float*)d_in[0];
    const float* W1  = (const float*)d_in[1];
    const float* b1  = (const float*)d_in[2];
    const float* W2  = (const float*)d_in[3];
    const float* b2  = (const float*)d_in[4];
    const int*   phi = (const int*)d_in[5];
    const float* pi  = (const float*)d_in[6];
    float* out = (float*)d_out;

    const int N = in_sizes[0] / NF;   // 131072

    cudaFuncSetAttribute(fused_all, cudaFuncAttributeMaxDynamicSharedMemorySize,
                         SMEM_TOTAL);

    prep_x<<<(size_t)N * NF / 4 / 256, 256>>>(X);     // 32768 blocks
    prep_w<<<384, 256>>>(W1, W2);
    fused_all<<<N / 128, 256, SMEM_TOTAL>>>(b1, b2, phi, pi, out);
}

// round 10
// speedup vs baseline: 1.3940x; 1.3630x over previous
#include <cuda_runtime.h>
#include <cuda_bf16.h>
#include <cstdint>

// Shapes: X[131072,256], W1[256,384], b1[384], W2[384,64], b2[64],
//         phi[5,64] i32, pi[5,64,16], out[131072,16]
#define NF  256
#define NH  384
#define NL  64
#define NO  16
#define NE  5

#define KS2 72           // k-stride (elems) for 64-k stage tiles (144 B rows)
#define KS  136          // k-stride (elems) for Hs (128-k, 272 B rows)

// ---------------------------------------------------------------------------
// Pre-split global tables (bf16 hi/lo), written by prep kernels each launch.
// ---------------------------------------------------------------------------
__device__ __align__(16) __nv_bfloat16 gXhi[131072UL * 256UL];
__device__ __align__(16) __nv_bfloat16 gXlo[131072UL * 256UL];
__device__ __align__(16) __nv_bfloat16 gW1[2][98304];   // [nc][k4][n128][k64]
__device__ __align__(16) __nv_bfloat16 gW2[2][24576];   // [nc][n64][k128]

__global__ void prep_x(const float* __restrict__ X) {
    size_t idx = (size_t)blockIdx.x * 256 + threadIdx.x;
    float4 v = *(const float4*)(X + idx * 4);
    __nv_bfloat162 h01 = __float22bfloat162_rn(make_float2(v.x, v.y));
    __nv_bfloat162 h23 = __float22bfloat162_rn(make_float2(v.z, v.w));
    __nv_bfloat162 l01 = __float22bfloat162_rn(make_float2(
        v.x - __bfloat162float(h01.x), v.y - __bfloat162float(h01.y)));
    __nv_bfloat162 l23 = __float22bfloat162_rn(make_float2(
        v.z - __bfloat162float(h23.x), v.w - __bfloat162float(h23.y)));
    uint2 hp, lp;
    hp.x = *(uint32_t*)&h01; hp.y = *(uint32_t*)&h23;
    lp.x = *(uint32_t*)&l01; lp.y = *(uint32_t*)&l23;
    *(uint2*)(gXhi + idx * 4) = hp;
    *(uint2*)(gXlo + idx * 4) = lp;
}

__global__ void prep_w(const float* __restrict__ W1, const float* __restrict__ W2) {
    int idx = blockIdx.x * 256 + threadIdx.x;
    if (idx < 98304) {
        int k  = idx & 63;
        int n  = (idx >> 6) & 127;
        int k4 = (idx >> 13) & 3;
        int nc = idx >> 15;
        float v = W1[(size_t)(k4 * 64 + k) * NH + nc * 128 + n];
        __nv_bfloat16 hi = __float2bfloat16(v);
        __nv_bfloat16 lo = __float2bfloat16(v - __bfloat162float(hi));
        gW1[0][idx] = hi;
        gW1[1][idx] = lo;
    }
    if (idx < 24576) {
        int k  = idx & 127;
        int n  = (idx >> 7) & 63;
        int nc = idx >> 13;
        float v = W2[(size_t)(nc * 128 + k) * NL + n];
        __nv_bfloat16 hi = __float2bfloat16(v);
        __nv_bfloat16 lo = __float2bfloat16(v - __bfloat162float(hi));
        gW2[0][idx] = hi;
        gW2[1][idx] = lo;
    }
}

// ---------------------------------------------------------------------------
// PTX helpers
// ---------------------------------------------------------------------------
__device__ __forceinline__ uint32_t smem_u32(const void* p) {
    uint32_t a;
    asm("{ .reg .u64 t; cvta.to.shared.u64 t, %1; cvt.u32.u64 %0, t; }"
        : "=r"(a) : "l"(p));
    return a;
}

#define CP16(dst, src) \
    asm volatile("cp.async.cg.shared.global [%0], [%1], 16;" :: "r"(dst), "l"(src))
#define CP_COMMIT() asm volatile("cp.async.commit_group;" ::: "memory")
#define CP_WAIT0()  asm volatile("cp.async.wait_group 0;" ::: "memory")

#define LDM_X4(r, addr) \
    asm volatile("ldmatrix.sync.aligned.m8n8.x4.shared.b16 {%0,%1,%2,%3}, [%4];" \
        : "=r"((r)[0]), "=r"((r)[1]), "=r"((r)[2]), "=r"((r)[3]) : "r"(addr))

__device__ __forceinline__ void mma_bf16(float* c, const uint32_t* a, const uint32_t* b) {
    asm volatile("mma.sync.aligned.m16n8k16.row.col.f32.bf16.bf16.f32 "
        "{%0,%1,%2,%3}, {%4,%5,%6,%7}, {%8,%9}, {%0,%1,%2,%3};"
        : "+f"(c[0]), "+f"(c[1]), "+f"(c[2]), "+f"(c[3])
        : "r"(a[0]), "r"(a[1]), "r"(a[2]), "r"(a[3]), "r"(b[0]), "r"(b[1]));
}

__device__ __forceinline__ float fsigmoid(float v) {
    return 1.0f / (1.0f + __expf(-v));
}

// ---------------------------------------------------------------------------
// SMEM layout (bytes), 111616 total -> 2 CTAs/SM:
//   SM_BUF = 0      : stage buffer 73728
//                     [XH 18432][XL 18432][W1H 18432][W1L 18432]  (128 x KS2)
//                     after GEMM1: Hs hi (34816) @0, Hs lo @34816
//                     after GEMM2: lat [128][65] f32 (33280) @0
//   SM_W2  = 73728  : W2 hi 17408, lo 17408  (64n x KS)
//   SM_PHI = 108544 (1280) | SM_B1 = 109824 (1536) | SM_B2 = 111360 (256)
// ---------------------------------------------------------------------------
#define XBUF    18432
#define SM_BUF  0
#define SM_W2   73728
#define SM_PHI  108544
#define SM_B1   109824
#define SM_B2   111360
#define SMEM_TOTAL 111616

__device__ __forceinline__ void issue_g1(uint32_t sbuf, int nc, int k4,
                                         size_t rowBase, int tid) {
#pragma unroll
    for (int i = 0; i < 4; i++) {
        int j = tid + i * 256;
        int row = j >> 3, c = j & 7;
        const __nv_bfloat16* sh = gXhi + (rowBase + row) * NF + k4 * 64 + c * 8;
        const __nv_bfloat16* sl = gXlo + (rowBase + row) * NF + k4 * 64 + c * 8;
        uint32_t d = sbuf + row * 144 + c * 16;
        CP16(d, sh);
        CP16(d + XBUF, sl);
    }
    const int wbase = ((nc * 4 + k4) * 128) * 64;
#pragma unroll
    for (int i = 0; i < 4; i++) {
        int j = tid + i * 256;
        int n = j >> 3, c = j & 7;
        uint32_t d = sbuf + 2 * XBUF + n * 144 + c * 16;
        CP16(d,        gW1[0] + wbase + n * 64 + c * 8);
        CP16(d + XBUF, gW1[1] + wbase + n * 64 + c * 8);
    }
    CP_COMMIT();
}

__device__ __forceinline__ void issue_w2(uint32_t sb, int nc, int tid) {
#pragma unroll
    for (int i = 0; i < 4; i++) {
        int j = tid + i * 256;
        int n = j >> 4, c = j & 15;
        uint32_t d = sb + SM_W2 + n * 272 + c * 16;
        CP16(d,         gW2[0] + (nc * 64 + n) * 128 + c * 8);
        CP16(d + 17408, gW2[1] + (nc * 64 + n) * 128 + c * 8);
    }
    CP_COMMIT();
}

__global__ __launch_bounds__(256, 2)
void fused_all(const float* __restrict__ b1, const float* __restrict__ b2,
               const int* __restrict__ phi, const float* __restrict__ pi,
               float* __restrict__ out) {
    extern __shared__ char smem[];
    const uint32_t sb = smem_u32(smem);
    const int tid = threadIdx.x;
    const int wid = tid >> 5;
    const int lane = tid & 31;
    const int g = lane >> 2;
    const int tg = lane & 3;
    const size_t rowBase = (size_t)blockIdx.x * 128;

    const int a_dr = lane & 15;
    const int a_dc = (lane >> 4) * 8;
    const int b_dn = (lane & 7) + (lane >> 4) * 8;
    const int b_dk = ((lane >> 3) & 1) * 8;

    // GEMM1: 4x2 warp grid, 32 rows x 64 cols per warp
    const int wm = (wid & 3) * 32;
    const int wn = (wid >> 2) * 64;
    // GEMM2: 8x1 grid, 16 rows x 64 cols per warp
    const int wm2 = wid * 16;

    // ---- stage constants ----
    {
        int* phis = (int*)(smem + SM_PHI);
        for (int i = tid; i < NE * NL; i += 256) phis[i] = phi[i];
        float* b1s = (float*)(smem + SM_B1);
        for (int i = tid; i < NH; i += 256) b1s[i] = b1[i];
        float* b2s = (float*)(smem + SM_B2);
        if (tid < NL) b2s[tid] = b2[tid];
    }

    const float* b1s = (const float*)(smem + SM_B1);
    const float* b2s = (const float*)(smem + SM_B2);

    float acc2[8][4];
#pragma unroll
    for (int n = 0; n < 8; n++)
#pragma unroll
        for (int r = 0; r < 4; r++) acc2[n][r] = 0.0f;

#pragma unroll 1
    for (int nc = 0; nc < 3; nc++) {
        float acc1[2][8][4];
#pragma unroll
        for (int m = 0; m < 2; m++)
#pragma unroll
            for (int n = 0; n < 8; n++)
#pragma unroll
                for (int r = 0; r < 4; r++) acc1[m][n][r] = 0.0f;

        issue_w2(sb, nc, tid);     // dedicated region, arrives with stage 0

#pragma unroll 1
        for (int k4 = 0; k4 < 4; k4++) {
            issue_g1(sb + SM_BUF, nc, k4, rowBase, tid);
            CP_WAIT0();
            __syncthreads();

            // ---- GEMM1 mma on this stage: 3 passes, B frags streamed ----
#pragma unroll 1
            for (int pass = 0; pass < 3; pass++) {
                uint32_t Ab = sb + SM_BUF + (pass == 2 ? XBUF : 0)
                            + ((wm + a_dr) * KS2 + a_dc) * 2;
                uint32_t Bb = sb + SM_BUF + 2 * XBUF + (pass == 1 ? XBUF : 0)
                            + ((wn + b_dn) * KS2 + b_dk) * 2;
#pragma unroll
                for (int k16 = 0; k16 < 4; k16++) {
                    uint32_t a0[4], a1[4];
                    LDM_X4(a0, Ab + k16 * 32);
                    LDM_X4(a1, Ab + k16 * 32 + 16 * KS2 * 2);
#pragma unroll
                    for (int p = 0; p < 4; p++) {
                        uint32_t bq[4];
                        LDM_X4(bq, Bb + k16 * 32 + p * 16 * KS2 * 2);
                        mma_bf16(acc1[0][2 * p],     a0, bq);
                        mma_bf16(acc1[0][2 * p + 1], a0, bq + 2);
                        mma_bf16(acc1[1][2 * p],     a1, bq);
                        mma_bf16(acc1[1][2 * p + 1], a1, bq + 2);
                    }
                }
            }
            __syncthreads();   // buffer reads done before next stage overwrites
        }

        // ---- epilogue1: h = sigmoid(acc1 + b1) -> Hs hi/lo (overlays BUF) ----
#pragma unroll
        for (int m = 0; m < 2; m++) {
            int row0 = wm + m * 16 + g;
#pragma unroll
            for (int n = 0; n < 8; n++) {
                int col = wn + n * 8 + 2 * tg;
                float bb0 = b1s[nc * 128 + col];
                float bb1 = b1s[nc * 128 + col + 1];
                float f0 = fsigmoid(acc1[m][n][0] + bb0);
                float f1 = fsigmoid(acc1[m][n][1] + bb1);
                float f2 = fsigmoid(acc1[m][n][2] + bb0);
                float f3 = fsigmoid(acc1[m][n][3] + bb1);
                __nv_bfloat162 h01 = __float22bfloat162_rn(make_float2(f0, f1));
                __nv_bfloat162 h23 = __float22bfloat162_rn(make_float2(f2, f3));
                __nv_bfloat162 l01 = __float22bfloat162_rn(make_float2(
                    f0 - __bfloat162float(h01.x), f1 - __bfloat162float(h01.y)));
                __nv_bfloat162 l23 = __float22bfloat162_rn(make_float2(
                    f2 - __bfloat162float(h23.x), f3 - __bfloat162float(h23.y)));
                *(uint32_t*)(smem + SM_BUF + (row0 * KS + col) * 2)               = *(uint32_t*)&h01;
                *(uint32_t*)(smem + SM_BUF + ((row0 + 8) * KS + col) * 2)         = *(uint32_t*)&h23;
                *(uint32_t*)(smem + SM_BUF + 34816 + (row0 * KS + col) * 2)       = *(uint32_t*)&l01;
                *(uint32_t*)(smem + SM_BUF + 34816 + ((row0 + 8) * KS + col) * 2) = *(uint32_t*)&l23;
            }
        }
        __syncthreads();       // Hs visible (W2 arrived with stage-0 wait)

        // ---- GEMM2 mma: acc2 += Hc @ W2c, 3 passes, B streamed ----
#pragma unroll 1
        for (int pass = 0; pass < 3; pass++) {
            uint32_t Ab = sb + SM_BUF + (pass == 2 ? 34816 : 0)
                        + ((wm2 + a_dr) * KS + a_dc) * 2;
            uint32_t Bb = sb + SM_W2 + (pass == 1 ? 17408 : 0)
                        + (b_dn * KS + b_dk) * 2;
#pragma unroll
            for (int k16 = 0; k16 < 8; k16++) {
                uint32_t a0[4];
                LDM_X4(a0, Ab + k16 * 32);
#pragma unroll
                for (int p = 0; p < 4; p++) {
                    uint32_t bq[4];
                    LDM_X4(bq, Bb + k16 * 32 + p * 16 * KS * 2);
                    mma_bf16(acc2[2 * p],     a0, bq);
                    mma_bf16(acc2[2 * p + 1], a0, bq + 2);
                }
            }
        }
        __syncthreads();       // Hs/W2 reads done before next nc overwrites
    }

    // ---- latent = sigmoid(acc2 + b2) -> lat (overlays BUF) ----
    float* lat = (float*)(smem + SM_BUF);
#pragma unroll
    for (int n = 0; n < 8; n++) {
        int c0 = n * 8 + 2 * tg;
        lat[(wm2 + g) * 65 + c0]         = fsigmoid(acc2[n][0] + b2s[c0]);
        lat[(wm2 + g) * 65 + c0 + 1]     = fsigmoid(acc2[n][1] + b2s[c0 + 1]);
        lat[(wm2 + g + 8) * 65 + c0]     = fsigmoid(acc2[n][2] + b2s[c0]);
        lat[(wm2 + g + 8) * 65 + c0 + 1] = fsigmoid(acc2[n][3] + b2s[c0 + 1]);
    }
    __syncthreads();

    // ---- tree + pi contraction (pi via L1-cached global) ----
    {
        const int row = tid & 127;
        const int obase = (tid >> 7) * 8;   // 0 or 8
        const float* latrow = lat + row * 65;
        const int* phis = (const int*)(smem + SM_PHI);
        float accO[8];
#pragma unroll
        for (int o = 0; o < 8; o++) accO[o] = 0.0f;

#pragma unroll 1
        for (int e = 0; e < NE; e++) {
            const int* phie = phis + e * NL;
            float mu[64];
            mu[0] = 1.0f;
#pragma unroll
            for (int lev = 0; lev < 6; lev++) {
#pragma unroll
                for (int j = (1 << lev) - 1; j >= 0; j--) {
                    int node = (1 << lev) + j;
                    float d = latrow[phie[node]];
                    float p = mu[j];
                    mu[2 * j + 1] = p * (1.0f - d);
                    mu[2 * j]     = p * d;
                }
            }
            const float* pie = pi + e * NL * NO + obase;
#pragma unroll
            for (int l = 0; l < NL; l++) {
                float m = mu[l];
                float4 p0 = __ldg((const float4*)(pie + l * NO));
                float4 p1 = __ldg((const float4*)(pie + l * NO + 4));
                accO[0] = fmaf(m, p0.x, accO[0]);
                accO[1] = fmaf(m, p0.y, accO[1]);
                accO[2] = fmaf(m, p0.z, accO[2]);
                accO[3] = fmaf(m, p0.w, accO[3]);
                accO[4] = fmaf(m, p1.x, accO[4]);
                accO[5] = fmaf(m, p1.y, accO[5]);
                accO[6] = fmaf(m, p1.z, accO[6]);
                accO[7] = fmaf(m, p1.w, accO[7]);
            }
        }
        float4 o0, o1;
        o0.x = accO[0] * 0.2f; o0.y = accO[1] * 0.2f;
        o0.z = accO[2] * 0.2f; o0.w = accO[3] * 0.2f;
        o1.x = accO[4] * 0.2f; o1.y = accO[5] * 0.2f;
        o1.z = accO[6] * 0.2f; o1.w = accO[7] * 0.2f;
        float* op = out + (rowBase + row) * NO + obase;
        *(float4*)op       = o0;
        *(float4*)(op + 4) = o1;
    }
}

// ---------------------------------------------------------------------------
extern "C" void kernel_launch(void* const* d_in, const int* in_sizes, int n_in,
                              void* d_out, int out_size) {
    const float* X   = (const float*)d_in[0];
    const float* W1  = (const float*)d_in[1];
    const float* b1  = (const float*)d_in[2];
    const float* W2  = (const float*)d_in[3];
    const float* b2  = (const float*)d_in[4];
    const int*   phi = (const int*)d_in[5];
    const float* pi  = (const float*)d_in[6];
    float* out = (float*)d_out;

    const int N = in_sizes[0] / NF;   // 131072

    cudaFuncSetAttribute(fused_all, cudaFuncAttributeMaxDynamicSharedMemorySize,
                         SMEM_TOTAL);

    prep_x<<<(size_t)N * NF / 4 / 256, 256>>>(X);
    prep_w<<<384, 256>>>(W1, W2);
    fused_all<<<N / 128, 256, SMEM_TOTAL>>>(b1, b2, phi, pi, out);
}